// round 1
// baseline (speedup 1.0000x reference)
#include <cuda_runtime.h>
#include <math.h>

#define T_DIM 2048
#define E_DIM 1024
#define H_DIM 16
#define D_DIM 64
#define F_DIM 4096
#define LN_EPS 1e-5f

// ---------------- scratch (device globals; allocation-free) ----------------
__device__ float g_q[H_DIM * T_DIM * D_DIM];       // [H][T][D]
__device__ float g_k[H_DIM * T_DIM * D_DIM];
__device__ float g_v[H_DIM * T_DIM * D_DIM];
__device__ float g_concat[T_DIM * H_DIM * D_DIM];  // [T][H*D]
__device__ float g_attn[T_DIM * E_DIM];
__device__ float g_hbuf[T_DIM * E_DIM];
__device__ float g_ffn1[T_DIM * F_DIM];
__device__ float g_ffn2[T_DIM * E_DIM];

// ---------------- generic tiled fp32 GEMM: C = A @ B (+bias)(+relu) --------
// A: [M,K] row-major (shared across z). B: [K,N] row-major, base + z*sB.
// C: [M,N] row-major, base + z*sC. flags: 1=bias, 2=relu.
__global__ void gemm_kernel(const float* __restrict__ A, const float* __restrict__ Bm,
                            const float* __restrict__ bias, float* __restrict__ Cm,
                            int M, int N, int K, long sB, long sC, int flags)
{
    const int BM = 64, BN = 64, BK = 16;
    __shared__ float As[BK][BM + 1];
    __shared__ float Bs[BK][BN];

    const int bx = blockIdx.x, by = blockIdx.y, bz = blockIdx.z;
    const float* B = Bm + (long)bz * sB;
    float* C = Cm + (long)bz * sC;

    const int tid = threadIdx.x;
    const int tx = tid & 15;         // 0..15 -> col group
    const int ty = tid >> 4;         // 0..15 -> row group

    float acc[4][4] = {};

    const float* Ablk = A + (long)(by * BM) * K;
    const float* Bblk = B + bx * BN;

    for (int k0 = 0; k0 < K; k0 += BK) {
        #pragma unroll
        for (int u = 0; u < 4; u++) {
            int idx = tid + 256 * u;
            int r = idx >> 4, c = idx & 15;                 // 64 rows x 16 k
            As[c][r] = Ablk[(long)r * K + k0 + c];
        }
        #pragma unroll
        for (int u = 0; u < 4; u++) {
            int idx = tid + 256 * u;
            int r = idx >> 6, c = idx & 63;                 // 16 k x 64 cols
            Bs[r][c] = Bblk[(long)(k0 + r) * N + c];
        }
        __syncthreads();

        #pragma unroll
        for (int kk = 0; kk < BK; kk++) {
            float a[4], b[4];
            #pragma unroll
            for (int i = 0; i < 4; i++) a[i] = As[kk][ty * 4 + i];
            #pragma unroll
            for (int j = 0; j < 4; j++) b[j] = Bs[kk][tx * 4 + j];
            #pragma unroll
            for (int i = 0; i < 4; i++)
                #pragma unroll
                for (int j = 0; j < 4; j++)
                    acc[i][j] += a[i] * b[j];
        }
        __syncthreads();
    }

    #pragma unroll
    for (int i = 0; i < 4; i++) {
        int row = by * BM + ty * 4 + i;
        #pragma unroll
        for (int j = 0; j < 4; j++) {
            int col = bx * BN + tx * 4 + j;
            float v = acc[i][j];
            if (flags & 1) v += bias[col];
            if (flags & 2) v = fmaxf(v, 0.0f);
            C[(long)row * N + col] = v;
        }
    }
}

// ---------------- causal flash attention: one warp per (t, h) --------------
// q,k,v: [H][T][D] fp32. out: [T][H*D] (concat layout). scale folded into q.
__global__ void attn_kernel(const float* __restrict__ q, const float* __restrict__ k,
                            const float* __restrict__ v, float* __restrict__ outc)
{
    const int t = blockIdx.x;
    const int h = blockIdx.y;
    const int lane = threadIdx.x;

    const float* kbase = k + (long)h * T_DIM * D_DIM;
    const float* vbase = v + (long)h * T_DIM * D_DIM;
    const float4* qrow = (const float4*)(q + ((long)h * T_DIM + t) * D_DIM);

    // full q row in registers, pre-scaled by 1/sqrt(D)=0.125
    float4 q4[16];
    #pragma unroll
    for (int i = 0; i < 16; i++) {
        float4 a = qrow[i];
        a.x *= 0.125f; a.y *= 0.125f; a.z *= 0.125f; a.w *= 0.125f;
        q4[i] = a;
    }

    float m = -INFINITY, l = 0.0f;
    float4 o4[16];
    #pragma unroll
    for (int i = 0; i < 16; i++) o4[i] = make_float4(0.f, 0.f, 0.f, 0.f);

    for (int j = lane; j <= t; j += 32) {
        const float4* krow = (const float4*)(kbase + (long)j * D_DIM);
        float s = 0.0f;
        #pragma unroll
        for (int i = 0; i < 16; i++) {
            float4 kk = krow[i];
            s += q4[i].x * kk.x + q4[i].y * kk.y + q4[i].z * kk.z + q4[i].w * kk.w;
        }

        float p;
        if (s > m) {
            float sc = __expf(m - s);   // 0 on first key (m=-inf)
            l *= sc;
            #pragma unroll
            for (int i = 0; i < 16; i++) {
                o4[i].x *= sc; o4[i].y *= sc; o4[i].z *= sc; o4[i].w *= sc;
            }
            m = s;
            p = 1.0f;
        } else {
            p = __expf(s - m);
        }
        l += p;

        const float4* vrow = (const float4*)(vbase + (long)j * D_DIM);
        #pragma unroll
        for (int i = 0; i < 16; i++) {
            float4 vv = vrow[i];
            o4[i].x += p * vv.x; o4[i].y += p * vv.y;
            o4[i].z += p * vv.z; o4[i].w += p * vv.w;
        }
    }

    // merge lanes: global max, rescale, sum l, sum o via smem transpose
    float mall = m;
    #pragma unroll
    for (int off = 16; off; off >>= 1)
        mall = fmaxf(mall, __shfl_xor_sync(0xffffffffu, mall, off));
    float f = __expf(m - mall);          // 0 for lanes with no keys
    float lf = l * f;
    #pragma unroll
    for (int off = 16; off; off >>= 1)
        lf += __shfl_xor_sync(0xffffffffu, lf, off);
    float inv = 1.0f / lf;

    __shared__ float sh[32][65];
    #pragma unroll
    for (int i = 0; i < 16; i++) {
        sh[lane][4 * i + 0] = o4[i].x * f;
        sh[lane][4 * i + 1] = o4[i].y * f;
        sh[lane][4 * i + 2] = o4[i].z * f;
        sh[lane][4 * i + 3] = o4[i].w * f;
    }
    __syncwarp();

    float acc0 = 0.f, acc1 = 0.f;
    #pragma unroll
    for (int j = 0; j < 32; j++) {
        acc0 += sh[j][lane];
        acc1 += sh[j][lane + 32];
    }
    long obase = (long)t * (H_DIM * D_DIM) + h * D_DIM;
    outc[obase + lane]      = acc0 * inv;
    outc[obase + 32 + lane] = acc1 * inv;
}

// ---------------- fused residual add + LayerNorm ---------------------------
// out[row] = gamma * ((a+b) - mean)/sqrt(var+eps) + beta   (gamma scalar)
__global__ void add_ln_kernel(const float* __restrict__ a, const float* __restrict__ b,
                              const float* __restrict__ gamma, const float* __restrict__ beta,
                              float* __restrict__ out)
{
    const int row = blockIdx.x;
    const int tid = threadIdx.x;
    const float* ar = a + (long)row * E_DIM;
    const float* br = b + (long)row * E_DIM;

    float v[4];
    float s = 0.f, s2 = 0.f;
    #pragma unroll
    for (int u = 0; u < 4; u++) {
        int i = tid + 256 * u;
        float x = ar[i] + br[i];
        v[u] = x;
        s += x;
        s2 += x * x;
    }

    #pragma unroll
    for (int off = 16; off; off >>= 1) {
        s  += __shfl_xor_sync(0xffffffffu, s, off);
        s2 += __shfl_xor_sync(0xffffffffu, s2, off);
    }
    __shared__ float rs[8], rs2[8];
    int w = tid >> 5, ln = tid & 31;
    if (ln == 0) { rs[w] = s; rs2[w] = s2; }
    __syncthreads();
    s = 0.f; s2 = 0.f;
    #pragma unroll
    for (int i = 0; i < 8; i++) { s += rs[i]; s2 += rs2[i]; }

    const float mean = s * (1.0f / E_DIM);
    const float var  = s2 * (1.0f / E_DIM) - mean * mean;
    const float rstd = rsqrtf(var + LN_EPS);
    const float g = gamma[0];

    #pragma unroll
    for (int u = 0; u < 4; u++) {
        int i = tid + 256 * u;
        out[(long)row * E_DIM + i] = g * (v[u] - mean) * rstd + beta[i];
    }
}

// ---------------- launch ----------------------------------------------------
extern "C" void kernel_launch(void* const* d_in, const int* in_sizes, int n_in,
                              void* d_out, int out_size)
{
    const float* x      = (const float*)d_in[0];
    const float* wq     = (const float*)d_in[1];
    const float* wk     = (const float*)d_in[2];
    const float* wv     = (const float*)d_in[3];
    const float* pool_w = (const float*)d_in[4];
    const float* l1_w   = (const float*)d_in[5];
    const float* l1_b   = (const float*)d_in[6];
    const float* l2_w   = (const float*)d_in[7];
    const float* l2_b   = (const float*)d_in[8];
    const float* gamma  = (const float*)d_in[9];
    const float* beta   = (const float*)d_in[10];
    float* out = (float*)d_out;

    float *q, *k, *v, *concat, *attn, *hbuf, *ffn1, *ffn2;
    cudaGetSymbolAddress((void**)&q,      g_q);
    cudaGetSymbolAddress((void**)&k,      g_k);
    cudaGetSymbolAddress((void**)&v,      g_v);
    cudaGetSymbolAddress((void**)&concat, g_concat);
    cudaGetSymbolAddress((void**)&attn,   g_attn);
    cudaGetSymbolAddress((void**)&hbuf,   g_hbuf);
    cudaGetSymbolAddress((void**)&ffn1,   g_ffn1);
    cudaGetSymbolAddress((void**)&ffn2,   g_ffn2);

    // 1) per-head QKV projections: x[T,E] @ w[h][E,D] -> [H][T][D]
    dim3 gq(1, T_DIM / 64, H_DIM);
    gemm_kernel<<<gq, 256>>>(x, wq, nullptr, q, T_DIM, D_DIM, E_DIM,
                             (long)E_DIM * D_DIM, (long)T_DIM * D_DIM, 0);
    gemm_kernel<<<gq, 256>>>(x, wk, nullptr, k, T_DIM, D_DIM, E_DIM,
                             (long)E_DIM * D_DIM, (long)T_DIM * D_DIM, 0);
    gemm_kernel<<<gq, 256>>>(x, wv, nullptr, v, T_DIM, D_DIM, E_DIM,
                             (long)E_DIM * D_DIM, (long)T_DIM * D_DIM, 0);

    // 2) causal attention -> concat [T, H*D]
    attn_kernel<<<dim3(T_DIM, H_DIM), 32>>>(q, k, v, concat);

    // 3) pooling projection: concat @ pool_w -> attn_out [T,E]
    gemm_kernel<<<dim3(E_DIM / 64, T_DIM / 64, 1), 256>>>(
        concat, pool_w, nullptr, attn, T_DIM, E_DIM, E_DIM, 0, 0, 0);

    // 4) h = LN(x + attn_out)
    add_ln_kernel<<<T_DIM, 256>>>(x, attn, gamma, beta, hbuf);

    // 5) ffn1 = relu(h @ l1_w + l1_b) [T,F]
    gemm_kernel<<<dim3(F_DIM / 64, T_DIM / 64, 1), 256>>>(
        hbuf, l1_w, l1_b, ffn1, T_DIM, F_DIM, E_DIM, 0, 0, 3);

    // 6) ffn2 = ffn1 @ l2_w + l2_b [T,E]
    gemm_kernel<<<dim3(E_DIM / 64, T_DIM / 64, 1), 256>>>(
        ffn1, l2_w, l2_b, ffn2, T_DIM, E_DIM, F_DIM, 0, 0, 1);

    // 7) out = LN(h + ffn2)
    add_ln_kernel<<<T_DIM, 256>>>(hbuf, ffn2, gamma, beta, out);
}

// round 3
// speedup vs baseline: 4.2313x; 4.2313x over previous
#include <cuda_runtime.h>
#include <math.h>
#include <stdint.h>

#define T_DIM 2048
#define E_DIM 1024
#define H_DIM 16
#define D_DIM 64
#define F_DIM 4096
#define LN_EPS 1e-5f

// ---------------- scratch (device globals; allocation-free) ----------------
__device__ float g_q[H_DIM * T_DIM * D_DIM];       // [H][T][D]
__device__ float g_k[H_DIM * T_DIM * D_DIM];
__device__ float g_v[H_DIM * T_DIM * D_DIM];
__device__ float g_concat[T_DIM * H_DIM * D_DIM];  // [T][H*D]
__device__ float g_attn[T_DIM * E_DIM];
__device__ float g_hbuf[T_DIM * E_DIM];
__device__ float g_ffn1[T_DIM * F_DIM];
__device__ float g_ffn2[T_DIM * E_DIM];

__device__ __forceinline__ float tf32r(float x) {
    float y;
    asm("cvt.rna.tf32.f32 %0, %1;" : "=f"(y) : "f"(x));
    return y;
}

__device__ __forceinline__ void mma_tf32(float c[4], uint32_t a0, uint32_t a1,
                                         uint32_t a2, uint32_t a3,
                                         uint32_t b0, uint32_t b1) {
    asm volatile(
        "mma.sync.aligned.m16n8k8.row.col.f32.tf32.tf32.f32 "
        "{%0,%1,%2,%3}, {%4,%5,%6,%7}, {%8,%9}, {%0,%1,%2,%3};\n"
        : "+f"(c[0]), "+f"(c[1]), "+f"(c[2]), "+f"(c[3])
        : "r"(a0), "r"(a1), "r"(a2), "r"(a3), "r"(b0), "r"(b1));
}

// ---------------- tf32 tensor-core GEMM: C = A @ B (+bias)(+relu) ----------
// A:[M,K] rm (shared over z). B:[K,N] rm, base+z*sB. C:[M,N] rm, base+z*sC.
// BM=128 BN=64 BK=16, 256 threads, 8 warps (4m x 2n), warp tile 32x32.
__global__ void __launch_bounds__(256)
gemm_tf32(const float* __restrict__ A, const float* __restrict__ Bm,
          const float* __restrict__ bias, float* __restrict__ Cm,
          int M, int N, int K, long sB, long sC, int flags)
{
    __shared__ float As[16][132];   // [k][m]
    __shared__ float Bs[16][68];    // [k][n]

    const float* B = Bm + (long)blockIdx.z * sB;
    float* C = Cm + (long)blockIdx.z * sC;

    const int tid = threadIdx.x;
    const int warp = tid >> 5, lane = tid & 31;
    const int g = lane >> 2, tig = lane & 3;
    const int wm = (warp >> 1) * 32;  // m offset in tile
    const int wn = (warp & 1) * 32;   // n offset in tile

    float c[2][4][4];
    #pragma unroll
    for (int mt = 0; mt < 2; mt++)
        #pragma unroll
        for (int nt = 0; nt < 4; nt++)
            #pragma unroll
            for (int e = 0; e < 4; e++) c[mt][nt][e] = 0.0f;

    const int arow = tid >> 1, akq = (tid & 1) * 8;
    const float* Ag = A + (long)(blockIdx.y * 128 + arow) * K + akq;
    const int brow = tid >> 4, bcol = (tid & 15) * 4;
    const float* Bg = B + (long)brow * N + blockIdx.x * 64 + bcol;

    for (int k0 = 0; k0 < K; k0 += 16) {
        float4 av0 = *(const float4*)(Ag + k0);
        float4 av1 = *(const float4*)(Ag + k0 + 4);
        float4 bv = *(const float4*)(Bg + (long)k0 * N);

        As[akq + 0][arow] = tf32r(av0.x);
        As[akq + 1][arow] = tf32r(av0.y);
        As[akq + 2][arow] = tf32r(av0.z);
        As[akq + 3][arow] = tf32r(av0.w);
        As[akq + 4][arow] = tf32r(av1.x);
        As[akq + 5][arow] = tf32r(av1.y);
        As[akq + 6][arow] = tf32r(av1.z);
        As[akq + 7][arow] = tf32r(av1.w);

        float4 bw;
        bw.x = tf32r(bv.x); bw.y = tf32r(bv.y);
        bw.z = tf32r(bv.z); bw.w = tf32r(bv.w);
        *(float4*)&Bs[brow][bcol] = bw;
        __syncthreads();

        #pragma unroll
        for (int ks = 0; ks < 2; ks++) {
            const int kb = ks * 8;
            uint32_t af[2][4], bf[4][2];
            #pragma unroll
            for (int mt = 0; mt < 2; mt++) {
                int mb = wm + mt * 16;
                af[mt][0] = __float_as_uint(As[kb + tig][mb + g]);
                af[mt][1] = __float_as_uint(As[kb + tig][mb + g + 8]);
                af[mt][2] = __float_as_uint(As[kb + tig + 4][mb + g]);
                af[mt][3] = __float_as_uint(As[kb + tig + 4][mb + g + 8]);
            }
            #pragma unroll
            for (int nt = 0; nt < 4; nt++) {
                int nb = wn + nt * 8;
                bf[nt][0] = __float_as_uint(Bs[kb + tig][nb + g]);
                bf[nt][1] = __float_as_uint(Bs[kb + tig + 4][nb + g]);
            }
            #pragma unroll
            for (int mt = 0; mt < 2; mt++)
                #pragma unroll
                for (int nt = 0; nt < 4; nt++)
                    mma_tf32(c[mt][nt], af[mt][0], af[mt][1], af[mt][2], af[mt][3],
                             bf[nt][0], bf[nt][1]);
        }
        __syncthreads();
    }

    #pragma unroll
    for (int mt = 0; mt < 2; mt++) {
        #pragma unroll
        for (int nt = 0; nt < 4; nt++) {
            int row0 = blockIdx.y * 128 + wm + mt * 16 + g;
            int col = blockIdx.x * 64 + wn + nt * 8 + tig * 2;
            float b0 = 0.f, b1 = 0.f;
            if (flags & 1) { b0 = bias[col]; b1 = bias[col + 1]; }
            float v00 = c[mt][nt][0] + b0, v01 = c[mt][nt][1] + b1;
            float v10 = c[mt][nt][2] + b0, v11 = c[mt][nt][3] + b1;
            if (flags & 2) {
                v00 = fmaxf(v00, 0.f); v01 = fmaxf(v01, 0.f);
                v10 = fmaxf(v10, 0.f); v11 = fmaxf(v11, 0.f);
            }
            *(float2*)&C[(long)row0 * N + col] = make_float2(v00, v01);
            *(float2*)&C[(long)(row0 + 8) * N + col] = make_float2(v10, v11);
        }
    }
}

// ---------------- tiled causal flash attention -----------------------------
// One block per (64-query tile, head). 256 threads in 16x16 grid; each thread
// owns a 4x4 microtile of the 64x64 score/prob tile and a 4x4 O microtile.
__global__ void __launch_bounds__(256)
attn_tile_kernel(const float* __restrict__ q, const float* __restrict__ k,
                 const float* __restrict__ v, float* __restrict__ outc)
{
    extern __shared__ float sm[];
    float* Qs = sm;                  // 64*65
    float* Ks = Qs + 64 * 65;
    float* Vs = Ks + 64 * 65;
    float* Ps = Vs + 64 * 65;
    float* red = Ps + 64 * 65;       // 64*16
    float* mrow = red + 64 * 16;     // 64
    float* lrow = mrow + 64;         // 64
    float* srow = lrow + 64;         // 64 (rescale factor)

    const int q0 = blockIdx.x * 64;
    const int h = blockIdx.y;
    const int tid = threadIdx.x;
    const int tx = tid & 15, ty = tid >> 4;

    const float* qbase = q + ((long)h * T_DIM + q0) * D_DIM;
    const float* kbase = k + (long)h * T_DIM * D_DIM;
    const float* vbase = v + (long)h * T_DIM * D_DIM;

    // load Q tile, pre-scaled by 1/sqrt(D)
    #pragma unroll
    for (int u = 0; u < 4; u++) {
        int f4 = tid + 256 * u;
        int row = f4 >> 4, d4 = (f4 & 15) * 4;
        float4 a = *(const float4*)(qbase + (long)row * D_DIM + d4);
        Qs[row * 65 + d4 + 0] = a.x * 0.125f;
        Qs[row * 65 + d4 + 1] = a.y * 0.125f;
        Qs[row * 65 + d4 + 2] = a.z * 0.125f;
        Qs[row * 65 + d4 + 3] = a.w * 0.125f;
    }
    if (tid < 64) { mrow[tid] = -INFINITY; lrow[tid] = 0.0f; }

    float o[4][4];
    #pragma unroll
    for (int i = 0; i < 4; i++)
        #pragma unroll
        for (int j = 0; j < 4; j++) o[i][j] = 0.0f;

    for (int j0 = 0; j0 <= q0; j0 += 64) {
        __syncthreads();
        // load K and V tiles
        #pragma unroll
        for (int u = 0; u < 4; u++) {
            int f4 = tid + 256 * u;
            int row = f4 >> 4, d4 = (f4 & 15) * 4;
            float4 a = *(const float4*)(kbase + (long)(j0 + row) * D_DIM + d4);
            Ks[row * 65 + d4 + 0] = a.x; Ks[row * 65 + d4 + 1] = a.y;
            Ks[row * 65 + d4 + 2] = a.z; Ks[row * 65 + d4 + 3] = a.w;
            float4 b = *(const float4*)(vbase + (long)(j0 + row) * D_DIM + d4);
            Vs[row * 65 + d4 + 0] = b.x; Vs[row * 65 + d4 + 1] = b.y;
            Vs[row * 65 + d4 + 2] = b.z; Vs[row * 65 + d4 + 3] = b.w;
        }
        __syncthreads();

        // scores: s[i][j] = sum_d Qs[r_i][d] * Ks[c_j][d]
        float s[4][4];
        #pragma unroll
        for (int i = 0; i < 4; i++)
            #pragma unroll
            for (int j = 0; j < 4; j++) s[i][j] = 0.0f;

        for (int d = 0; d < 64; d++) {
            float a0 = Qs[(ty * 4 + 0) * 65 + d];
            float a1 = Qs[(ty * 4 + 1) * 65 + d];
            float a2 = Qs[(ty * 4 + 2) * 65 + d];
            float a3 = Qs[(ty * 4 + 3) * 65 + d];
            float b0 = Ks[(tx * 4 + 0) * 65 + d];
            float b1 = Ks[(tx * 4 + 1) * 65 + d];
            float b2 = Ks[(tx * 4 + 2) * 65 + d];
            float b3 = Ks[(tx * 4 + 3) * 65 + d];
            s[0][0] += a0 * b0; s[0][1] += a0 * b1; s[0][2] += a0 * b2; s[0][3] += a0 * b3;
            s[1][0] += a1 * b0; s[1][1] += a1 * b1; s[1][2] += a1 * b2; s[1][3] += a1 * b3;
            s[2][0] += a2 * b0; s[2][1] += a2 * b1; s[2][2] += a2 * b2; s[2][3] += a2 * b3;
            s[3][0] += a3 * b0; s[3][1] += a3 * b1; s[3][2] += a3 * b2; s[3][3] += a3 * b3;
        }

        if (j0 == q0) {  // causal mask within diagonal tile
            #pragma unroll
            for (int i = 0; i < 4; i++)
                #pragma unroll
                for (int j = 0; j < 4; j++)
                    if (tx * 4 + j > ty * 4 + i) s[i][j] = -1e30f;
        }

        // per-row max across the 16 column-threads
        #pragma unroll
        for (int i = 0; i < 4; i++) {
            float lm = fmaxf(fmaxf(s[i][0], s[i][1]), fmaxf(s[i][2], s[i][3]));
            red[(ty * 4 + i) * 16 + tx] = lm;
        }
        __syncthreads();
        if (tid < 64) {
            float mx = red[tid * 16];
            #pragma unroll
            for (int e = 1; e < 16; e++) mx = fmaxf(mx, red[tid * 16 + e]);
            float mo = mrow[tid];
            float mn = fmaxf(mo, mx);
            srow[tid] = __expf(mo - mn);   // 0 on first tile (mo=-inf)
            mrow[tid] = mn;
        }
        __syncthreads();

        // probs + row sums + O rescale
        #pragma unroll
        for (int i = 0; i < 4; i++) {
            int r = ty * 4 + i;
            float mn = mrow[r];
            float sc = srow[r];
            o[i][0] *= sc; o[i][1] *= sc; o[i][2] *= sc; o[i][3] *= sc;
            float rs = 0.0f;
            #pragma unroll
            for (int j = 0; j < 4; j++) {
                float p = __expf(s[i][j] - mn);
                Ps[r * 65 + tx * 4 + j] = p;
                rs += p;
            }
            red[r * 16 + tx] = rs;
        }
        __syncthreads();
        if (tid < 64) {
            float ls = 0.0f;
            #pragma unroll
            for (int e = 0; e < 16; e++) ls += red[tid * 16 + e];
            lrow[tid] = lrow[tid] * srow[tid] + ls;
        }

        // O += P @ V  (dims dd = tx*4..+3)
        for (int kk = 0; kk < 64; kk++) {
            float p0 = Ps[(ty * 4 + 0) * 65 + kk];
            float p1 = Ps[(ty * 4 + 1) * 65 + kk];
            float p2 = Ps[(ty * 4 + 2) * 65 + kk];
            float p3 = Ps[(ty * 4 + 3) * 65 + kk];
            float v0 = Vs[kk * 65 + tx * 4 + 0];
            float v1 = Vs[kk * 65 + tx * 4 + 1];
            float v2 = Vs[kk * 65 + tx * 4 + 2];
            float v3 = Vs[kk * 65 + tx * 4 + 3];
            o[0][0] += p0 * v0; o[0][1] += p0 * v1; o[0][2] += p0 * v2; o[0][3] += p0 * v3;
            o[1][0] += p1 * v0; o[1][1] += p1 * v1; o[1][2] += p1 * v2; o[1][3] += p1 * v3;
            o[2][0] += p2 * v0; o[2][1] += p2 * v1; o[2][2] += p2 * v2; o[2][3] += p2 * v3;
            o[3][0] += p3 * v0; o[3][1] += p3 * v1; o[3][2] += p3 * v2; o[3][3] += p3 * v3;
        }
    }
    __syncthreads();

    #pragma unroll
    for (int i = 0; i < 4; i++) {
        int r = ty * 4 + i;
        float inv = 1.0f / lrow[r];
        long base = (long)(q0 + r) * (H_DIM * D_DIM) + h * D_DIM + tx * 4;
        float4 w;
        w.x = o[i][0] * inv; w.y = o[i][1] * inv;
        w.z = o[i][2] * inv; w.w = o[i][3] * inv;
        *(float4*)&outc[base] = w;
    }
}

// ---------------- fused residual add + LayerNorm ---------------------------
__global__ void add_ln_kernel(const float* __restrict__ a, const float* __restrict__ b,
                              const float* __restrict__ gamma, const float* __restrict__ beta,
                              float* __restrict__ out)
{
    const int row = blockIdx.x;
    const int tid = threadIdx.x;
    const float* ar = a + (long)row * E_DIM;
    const float* br = b + (long)row * E_DIM;

    float v[4];
    float s = 0.f, s2 = 0.f;
    #pragma unroll
    for (int u = 0; u < 4; u++) {
        int i = tid + 256 * u;
        float x = ar[i] + br[i];
        v[u] = x;
        s += x;
        s2 += x * x;
    }
    #pragma unroll
    for (int off = 16; off; off >>= 1) {
        s  += __shfl_xor_sync(0xffffffffu, s, off);
        s2 += __shfl_xor_sync(0xffffffffu, s2, off);
    }
    __shared__ float rs[8], rs2[8];
    int w = tid >> 5, ln = tid & 31;
    if (ln == 0) { rs[w] = s; rs2[w] = s2; }
    __syncthreads();
    s = 0.f; s2 = 0.f;
    #pragma unroll
    for (int i = 0; i < 8; i++) { s += rs[i]; s2 += rs2[i]; }

    const float mean = s * (1.0f / E_DIM);
    const float var  = s2 * (1.0f / E_DIM) - mean * mean;
    const float rstd = rsqrtf(var + LN_EPS);
    const float gg = gamma[0];

    #pragma unroll
    for (int u = 0; u < 4; u++) {
        int i = tid + 256 * u;
        out[(long)row * E_DIM + i] = gg * (v[u] - mean) * rstd + beta[i];
    }
}

// ---------------- launch ----------------------------------------------------
extern "C" void kernel_launch(void* const* d_in, const int* in_sizes, int n_in,
                              void* d_out, int out_size)
{
    const float* x      = (const float*)d_in[0];
    const float* wq     = (const float*)d_in[1];
    const float* wk     = (const float*)d_in[2];
    const float* wv     = (const float*)d_in[3];
    const float* pool_w = (const float*)d_in[4];
    const float* l1_w   = (const float*)d_in[5];
    const float* l1_b   = (const float*)d_in[6];
    const float* l2_w   = (const float*)d_in[7];
    const float* l2_b   = (const float*)d_in[8];
    const float* gamma  = (const float*)d_in[9];
    const float* beta   = (const float*)d_in[10];
    float* out = (float*)d_out;

    float *q, *k, *v, *concat, *attn, *hbuf, *ffn1, *ffn2;
    cudaGetSymbolAddress((void**)&q,      g_q);
    cudaGetSymbolAddress((void**)&k,      g_k);
    cudaGetSymbolAddress((void**)&v,      g_v);
    cudaGetSymbolAddress((void**)&concat, g_concat);
    cudaGetSymbolAddress((void**)&attn,   g_attn);
    cudaGetSymbolAddress((void**)&hbuf,   g_hbuf);
    cudaGetSymbolAddress((void**)&ffn1,   g_ffn1);
    cudaGetSymbolAddress((void**)&ffn2,   g_ffn2);

    const int attn_smem = (4 * 64 * 65 + 64 * 16 + 3 * 64) * 4;
    cudaFuncSetAttribute(attn_tile_kernel,
                         cudaFuncAttributeMaxDynamicSharedMemorySize, attn_smem);

    // 1) per-head QKV projections
    dim3 gq(1, T_DIM / 128, H_DIM);
    gemm_tf32<<<gq, 256>>>(x, wq, nullptr, q, T_DIM, D_DIM, E_DIM,
                           (long)E_DIM * D_DIM, (long)T_DIM * D_DIM, 0);
    gemm_tf32<<<gq, 256>>>(x, wk, nullptr, k, T_DIM, D_DIM, E_DIM,
                           (long)E_DIM * D_DIM, (long)T_DIM * D_DIM, 0);
    gemm_tf32<<<gq, 256>>>(x, wv, nullptr, v, T_DIM, D_DIM, E_DIM,
                           (long)E_DIM * D_DIM, (long)T_DIM * D_DIM, 0);

    // 2) causal attention -> concat [T, H*D]
    attn_tile_kernel<<<dim3(T_DIM / 64, H_DIM), 256, attn_smem>>>(q, k, v, concat);

    // 3) pooling projection
    gemm_tf32<<<dim3(E_DIM / 64, T_DIM / 128, 1), 256>>>(
        concat, pool_w, nullptr, attn, T_DIM, E_DIM, E_DIM, 0, 0, 0);

    // 4) h = LN(x + attn_out)
    add_ln_kernel<<<T_DIM, 256>>>(x, attn, gamma, beta, hbuf);

    // 5) ffn1 = relu(h @ l1_w + l1_b)
    gemm_tf32<<<dim3(F_DIM / 64, T_DIM / 128, 1), 256>>>(
        hbuf, l1_w, l1_b, ffn1, T_DIM, F_DIM, E_DIM, 0, 0, 3);

    // 6) ffn2 = ffn1 @ l2_w + l2_b
    gemm_tf32<<<dim3(E_DIM / 64, T_DIM / 128, 1), 256>>>(
        ffn1, l2_w, l2_b, ffn2, T_DIM, E_DIM, F_DIM, 0, 0, 1);

    // 7) out = LN(h + ffn2)
    add_ln_kernel<<<T_DIM, 256>>>(hbuf, ffn2, gamma, beta, out);
}

// round 13
// speedup vs baseline: 5.7145x; 1.3505x over previous
#include <cuda_runtime.h>
#include <math.h>
#include <stdint.h>

#define T_DIM 2048
#define E_DIM 1024
#define H_DIM 16
#define D_DIM 64
#define F_DIM 4096
#define LN_EPS 1e-5f

// ---------------- scratch (device globals; allocation-free) ----------------
__device__ float g_q[H_DIM * T_DIM * D_DIM];       // [H][T][D]
__device__ float g_k[H_DIM * T_DIM * D_DIM];
__device__ float g_v[H_DIM * T_DIM * D_DIM];
__device__ float g_concat[T_DIM * H_DIM * D_DIM];  // [T][H*D]
__device__ float g_attn[T_DIM * E_DIM];
__device__ float g_hbuf[T_DIM * E_DIM];
__device__ float g_ffn1[T_DIM * F_DIM];
__device__ float g_ffn2[T_DIM * E_DIM];

__device__ __forceinline__ float tf32r(float x) {
    float y;
    asm("cvt.rna.tf32.f32 %0, %1;" : "=f"(y) : "f"(x));
    return y;
}

__device__ __forceinline__ void mma_tf32(float c[4], uint32_t a0, uint32_t a1,
                                         uint32_t a2, uint32_t a3,
                                         uint32_t b0, uint32_t b1) {
    asm volatile(
        "mma.sync.aligned.m16n8k8.row.col.f32.tf32.tf32.f32 "
        "{%0,%1,%2,%3}, {%4,%5,%6,%7}, {%8,%9}, {%0,%1,%2,%3};\n"
        : "+f"(c[0]), "+f"(c[1]), "+f"(c[2]), "+f"(c[3])
        : "r"(a0), "r"(a1), "r"(a2), "r"(a3), "r"(b0), "r"(b1));
}

// ---------------- tf32 tensor-core GEMM: C = A @ B (+bias)(+relu) ----------
// A:[M,K] rm (shared over z). B:[K,N] rm, base+z*sB. C:[M,N] rm, base+z*sC.
// BM=128 BN=64 BK=32, 256 threads, 8 warps (4m x 2n), warp tile 32x32.
// Double-buffered smem + register staging: one __syncthreads per K-tile.
#define AS_S 133
#define BS_S 72
#define GEMM_SMEM ((2 * 32 * AS_S + 2 * 32 * BS_S) * 4)

__global__ void __launch_bounds__(256)
gemm_tf32(const float* __restrict__ A, const float* __restrict__ Bm,
          const float* __restrict__ bias, float* __restrict__ Cm,
          int M, int N, int K, long sB, long sC, int flags)
{
    extern __shared__ float sm[];
    float* Asm = sm;                       // [2][32][AS_S]  ([k][m])
    float* Bsm = sm + 2 * 32 * AS_S;       // [2][32][BS_S]  ([k][n])

    const float* B = Bm + (long)blockIdx.z * sB;
    float* C = Cm + (long)blockIdx.z * sC;

    const int tid = threadIdx.x;
    const int warp = tid >> 5, lane = tid & 31;
    const int g = lane >> 2, tig = lane & 3;
    const int wm = (warp >> 1) * 32;
    const int wn = (warp & 1) * 32;

    float c[2][4][4];
    #pragma unroll
    for (int mt = 0; mt < 2; mt++)
        #pragma unroll
        for (int nt = 0; nt < 4; nt++)
            #pragma unroll
            for (int e = 0; e < 4; e++) c[mt][nt][e] = 0.0f;

    // global mappings (fully coalesced: warp = 4 rows x 128B for A, 2 rows x 256B for B)
    const int rowA = tid >> 3;            // + 32u
    const int kgA  = (tid & 7) * 4;       // k offset within tile
    const float* Agp = A + (long)(blockIdx.y * 128 + rowA) * K + kgA;
    const int rowB = tid >> 4;            // + 16u (k-row)
    const int cgB  = (tid & 15) * 4;
    const float* Bgp = B + (long)rowB * N + blockIdx.x * 64 + cgB;

    const int KT = K >> 5;
    float4 aS[4], bS[2];

    // prologue: stage tile 0
    #pragma unroll
    for (int u = 0; u < 4; u++) aS[u] = *(const float4*)(Agp + (long)(32 * u) * K);
    #pragma unroll
    for (int u = 0; u < 2; u++) bS[u] = *(const float4*)(Bgp + (long)(16 * u) * N);

    int buf = 0;
    for (int kt = 0; kt < KT; kt++) {
        // store staged tile to smem[buf] (converted to tf32)
        float* Ab = Asm + buf * (32 * AS_S);
        float* Bb = Bsm + buf * (32 * BS_S);
        #pragma unroll
        for (int u = 0; u < 4; u++) {
            int m = rowA + 32 * u;
            Ab[(kgA + 0) * AS_S + m] = tf32r(aS[u].x);
            Ab[(kgA + 1) * AS_S + m] = tf32r(aS[u].y);
            Ab[(kgA + 2) * AS_S + m] = tf32r(aS[u].z);
            Ab[(kgA + 3) * AS_S + m] = tf32r(aS[u].w);
        }
        #pragma unroll
        for (int u = 0; u < 2; u++) {
            int kr = rowB + 16 * u;
            float4 t;
            t.x = tf32r(bS[u].x); t.y = tf32r(bS[u].y);
            t.z = tf32r(bS[u].z); t.w = tf32r(bS[u].w);
            *(float4*)&Bb[kr * BS_S + cgB] = t;
        }
        __syncthreads();

        // stage next tile (LDGs overlap the mma loop below)
        if (kt + 1 < KT) {
            long k0 = (long)(kt + 1) * 32;
            #pragma unroll
            for (int u = 0; u < 4; u++)
                aS[u] = *(const float4*)(Agp + (long)(32 * u) * K + k0);
            #pragma unroll
            for (int u = 0; u < 2; u++)
                bS[u] = *(const float4*)(Bgp + (k0 + 16 * u) * N);
        }

        // mma over smem[buf]: 4 k8-steps
        #pragma unroll
        for (int ks = 0; ks < 4; ks++) {
            const int kb = ks * 8;
            uint32_t af[2][4], bf[4][2];
            #pragma unroll
            for (int mt = 0; mt < 2; mt++) {
                int mb = wm + mt * 16;
                af[mt][0] = __float_as_uint(Ab[(kb + tig) * AS_S + mb + g]);
                af[mt][1] = __float_as_uint(Ab[(kb + tig) * AS_S + mb + g + 8]);
                af[mt][2] = __float_as_uint(Ab[(kb + tig + 4) * AS_S + mb + g]);
                af[mt][3] = __float_as_uint(Ab[(kb + tig + 4) * AS_S + mb + g + 8]);
            }
            #pragma unroll
            for (int nt = 0; nt < 4; nt++) {
                int nb = wn + nt * 8;
                bf[nt][0] = __float_as_uint(Bb[(kb + tig) * BS_S + nb + g]);
                bf[nt][1] = __float_as_uint(Bb[(kb + tig + 4) * BS_S + nb + g]);
            }
            #pragma unroll
            for (int mt = 0; mt < 2; mt++)
                #pragma unroll
                for (int nt = 0; nt < 4; nt++)
                    mma_tf32(c[mt][nt], af[mt][0], af[mt][1], af[mt][2], af[mt][3],
                             bf[nt][0], bf[nt][1]);
        }
        buf ^= 1;
    }

    #pragma unroll
    for (int mt = 0; mt < 2; mt++) {
        #pragma unroll
        for (int nt = 0; nt < 4; nt++) {
            int row0 = blockIdx.y * 128 + wm + mt * 16 + g;
            int col = blockIdx.x * 64 + wn + nt * 8 + tig * 2;
            float b0 = 0.f, b1 = 0.f;
            if (flags & 1) { b0 = bias[col]; b1 = bias[col + 1]; }
            float v00 = c[mt][nt][0] + b0, v01 = c[mt][nt][1] + b1;
            float v10 = c[mt][nt][2] + b0, v11 = c[mt][nt][3] + b1;
            if (flags & 2) {
                v00 = fmaxf(v00, 0.f); v01 = fmaxf(v01, 0.f);
                v10 = fmaxf(v10, 0.f); v11 = fmaxf(v11, 0.f);
            }
            *(float2*)&C[(long)row0 * N + col] = make_float2(v00, v01);
            *(float2*)&C[(long)(row0 + 8) * N + col] = make_float2(v10, v11);
        }
    }
}

// ---------------- tiled causal flash attention (unchanged, passing) --------
__global__ void __launch_bounds__(256)
attn_tile_kernel(const float* __restrict__ q, const float* __restrict__ k,
                 const float* __restrict__ v, float* __restrict__ outc)
{
    extern __shared__ float sm[];
    float* Qs = sm;                  // 64*65
    float* Ks = Qs + 64 * 65;
    float* Vs = Ks + 64 * 65;
    float* Ps = Vs + 64 * 65;
    float* red = Ps + 64 * 65;       // 64*16
    float* mrow = red + 64 * 16;     // 64
    float* lrow = mrow + 64;         // 64
    float* srow = lrow + 64;         // 64

    const int q0 = blockIdx.x * 64;
    const int h = blockIdx.y;
    const int tid = threadIdx.x;
    const int tx = tid & 15, ty = tid >> 4;

    const float* qbase = q + ((long)h * T_DIM + q0) * D_DIM;
    const float* kbase = k + (long)h * T_DIM * D_DIM;
    const float* vbase = v + (long)h * T_DIM * D_DIM;

    #pragma unroll
    for (int u = 0; u < 4; u++) {
        int f4 = tid + 256 * u;
        int row = f4 >> 4, d4 = (f4 & 15) * 4;
        float4 a = *(const float4*)(qbase + (long)row * D_DIM + d4);
        Qs[row * 65 + d4 + 0] = a.x * 0.125f;
        Qs[row * 65 + d4 + 1] = a.y * 0.125f;
        Qs[row * 65 + d4 + 2] = a.z * 0.125f;
        Qs[row * 65 + d4 + 3] = a.w * 0.125f;
    }
    if (tid < 64) { mrow[tid] = -INFINITY; lrow[tid] = 0.0f; }

    float o[4][4];
    #pragma unroll
    for (int i = 0; i < 4; i++)
        #pragma unroll
        for (int j = 0; j < 4; j++) o[i][j] = 0.0f;

    for (int j0 = 0; j0 <= q0; j0 += 64) {
        __syncthreads();
        #pragma unroll
        for (int u = 0; u < 4; u++) {
            int f4 = tid + 256 * u;
            int row = f4 >> 4, d4 = (f4 & 15) * 4;
            float4 a = *(const float4*)(kbase + (long)(j0 + row) * D_DIM + d4);
            Ks[row * 65 + d4 + 0] = a.x; Ks[row * 65 + d4 + 1] = a.y;
            Ks[row * 65 + d4 + 2] = a.z; Ks[row * 65 + d4 + 3] = a.w;
            float4 b = *(const float4*)(vbase + (long)(j0 + row) * D_DIM + d4);
            Vs[row * 65 + d4 + 0] = b.x; Vs[row * 65 + d4 + 1] = b.y;
            Vs[row * 65 + d4 + 2] = b.z; Vs[row * 65 + d4 + 3] = b.w;
        }
        __syncthreads();

        float s[4][4];
        #pragma unroll
        for (int i = 0; i < 4; i++)
            #pragma unroll
            for (int j = 0; j < 4; j++) s[i][j] = 0.0f;

        for (int d = 0; d < 64; d++) {
            float a0 = Qs[(ty * 4 + 0) * 65 + d];
            float a1 = Qs[(ty * 4 + 1) * 65 + d];
            float a2 = Qs[(ty * 4 + 2) * 65 + d];
            float a3 = Qs[(ty * 4 + 3) * 65 + d];
            float b0 = Ks[(tx * 4 + 0) * 65 + d];
            float b1 = Ks[(tx * 4 + 1) * 65 + d];
            float b2 = Ks[(tx * 4 + 2) * 65 + d];
            float b3 = Ks[(tx * 4 + 3) * 65 + d];
            s[0][0] += a0 * b0; s[0][1] += a0 * b1; s[0][2] += a0 * b2; s[0][3] += a0 * b3;
            s[1][0] += a1 * b0; s[1][1] += a1 * b1; s[1][2] += a1 * b2; s[1][3] += a1 * b3;
            s[2][0] += a2 * b0; s[2][1] += a2 * b1; s[2][2] += a2 * b2; s[2][3] += a2 * b3;
            s[3][0] += a3 * b0; s[3][1] += a3 * b1; s[3][2] += a3 * b2; s[3][3] += a3 * b3;
        }

        if (j0 == q0) {
            #pragma unroll
            for (int i = 0; i < 4; i++)
                #pragma unroll
                for (int j = 0; j < 4; j++)
                    if (tx * 4 + j > ty * 4 + i) s[i][j] = -1e30f;
        }

        #pragma unroll
        for (int i = 0; i < 4; i++) {
            float lm = fmaxf(fmaxf(s[i][0], s[i][1]), fmaxf(s[i][2], s[i][3]));
            red[(ty * 4 + i) * 16 + tx] = lm;
        }
        __syncthreads();
        if (tid < 64) {
            float mx = red[tid * 16];
            #pragma unroll
            for (int e = 1; e < 16; e++) mx = fmaxf(mx, red[tid * 16 + e]);
            float mo = mrow[tid];
            float mn = fmaxf(mo, mx);
            srow[tid] = __expf(mo - mn);
            mrow[tid] = mn;
        }
        __syncthreads();

        #pragma unroll
        for (int i = 0; i < 4; i++) {
            int r = ty * 4 + i;
            float mn = mrow[r];
            float sc = srow[r];
            o[i][0] *= sc; o[i][1] *= sc; o[i][2] *= sc; o[i][3] *= sc;
            float rs = 0.0f;
            #pragma unroll
            for (int j = 0; j < 4; j++) {
                float p = __expf(s[i][j] - mn);
                Ps[r * 65 + tx * 4 + j] = p;
                rs += p;
            }
            red[r * 16 + tx] = rs;
        }
        __syncthreads();
        if (tid < 64) {
            float ls = 0.0f;
            #pragma unroll
            for (int e = 0; e < 16; e++) ls += red[tid * 16 + e];
            lrow[tid] = lrow[tid] * srow[tid] + ls;
        }

        for (int kk = 0; kk < 64; kk++) {
            float p0 = Ps[(ty * 4 + 0) * 65 + kk];
            float p1 = Ps[(ty * 4 + 1) * 65 + kk];
            float p2 = Ps[(ty * 4 + 2) * 65 + kk];
            float p3 = Ps[(ty * 4 + 3) * 65 + kk];
            float v0 = Vs[kk * 65 + tx * 4 + 0];
            float v1 = Vs[kk * 65 + tx * 4 + 1];
            float v2 = Vs[kk * 65 + tx * 4 + 2];
            float v3 = Vs[kk * 65 + tx * 4 + 3];
            o[0][0] += p0 * v0; o[0][1] += p0 * v1; o[0][2] += p0 * v2; o[0][3] += p0 * v3;
            o[1][0] += p1 * v0; o[1][1] += p1 * v1; o[1][2] += p1 * v2; o[1][3] += p1 * v3;
            o[2][0] += p2 * v0; o[2][1] += p2 * v1; o[2][2] += p2 * v2; o[2][3] += p2 * v3;
            o[3][0] += p3 * v0; o[3][1] += p3 * v1; o[3][2] += p3 * v2; o[3][3] += p3 * v3;
        }
    }
    __syncthreads();

    #pragma unroll
    for (int i = 0; i < 4; i++) {
        int r = ty * 4 + i;
        float inv = 1.0f / lrow[r];
        long base = (long)(q0 + r) * (H_DIM * D_DIM) + h * D_DIM + tx * 4;
        float4 w;
        w.x = o[i][0] * inv; w.y = o[i][1] * inv;
        w.z = o[i][2] * inv; w.w = o[i][3] * inv;
        *(float4*)&outc[base] = w;
    }
}

// ---------------- fused residual add + LayerNorm ---------------------------
__global__ void add_ln_kernel(const float* __restrict__ a, const float* __restrict__ b,
                              const float* __restrict__ gamma, const float* __restrict__ beta,
                              float* __restrict__ out)
{
    const int row = blockIdx.x;
    const int tid = threadIdx.x;
    const float* ar = a + (long)row * E_DIM;
    const float* br = b + (long)row * E_DIM;

    float v[4];
    float s = 0.f, s2 = 0.f;
    #pragma unroll
    for (int u = 0; u < 4; u++) {
        int i = tid + 256 * u;
        float x = ar[i] + br[i];
        v[u] = x;
        s += x;
        s2 += x * x;
    }
    #pragma unroll
    for (int off = 16; off; off >>= 1) {
        s  += __shfl_xor_sync(0xffffffffu, s, off);
        s2 += __shfl_xor_sync(0xffffffffu, s2, off);
    }
    __shared__ float rs[8], rs2[8];
    int w = tid >> 5, ln = tid & 31;
    if (ln == 0) { rs[w] = s; rs2[w] = s2; }
    __syncthreads();
    s = 0.f; s2 = 0.f;
    #pragma unroll
    for (int i = 0; i < 8; i++) { s += rs[i]; s2 += rs2[i]; }

    const float mean = s * (1.0f / E_DIM);
    const float var  = s2 * (1.0f / E_DIM) - mean * mean;
    const float rstd = rsqrtf(var + LN_EPS);
    const float gg = gamma[0];

    #pragma unroll
    for (int u = 0; u < 4; u++) {
        int i = tid + 256 * u;
        out[(long)row * E_DIM + i] = gg * (v[u] - mean) * rstd + beta[i];
    }
}

// ---------------- launch ----------------------------------------------------
extern "C" void kernel_launch(void* const* d_in, const int* in_sizes, int n_in,
                              void* d_out, int out_size)
{
    const float* x      = (const float*)d_in[0];
    const float* wq     = (const float*)d_in[1];
    const float* wk     = (const float*)d_in[2];
    const float* wv     = (const float*)d_in[3];
    const float* pool_w = (const float*)d_in[4];
    const float* l1_w   = (const float*)d_in[5];
    const float* l1_b   = (const float*)d_in[6];
    const float* l2_w   = (const float*)d_in[7];
    const float* l2_b   = (const float*)d_in[8];
    const float* gamma  = (const float*)d_in[9];
    const float* beta   = (const float*)d_in[10];
    float* out = (float*)d_out;

    float *q, *k, *v, *concat, *attn, *hbuf, *ffn1, *ffn2;
    cudaGetSymbolAddress((void**)&q,      g_q);
    cudaGetSymbolAddress((void**)&k,      g_k);
    cudaGetSymbolAddress((void**)&v,      g_v);
    cudaGetSymbolAddress((void**)&concat, g_concat);
    cudaGetSymbolAddress((void**)&attn,   g_attn);
    cudaGetSymbolAddress((void**)&hbuf,   g_hbuf);
    cudaGetSymbolAddress((void**)&ffn1,   g_ffn1);
    cudaGetSymbolAddress((void**)&ffn2,   g_ffn2);

    const int attn_smem = (4 * 64 * 65 + 64 * 16 + 3 * 64) * 4;
    cudaFuncSetAttribute(attn_tile_kernel,
                         cudaFuncAttributeMaxDynamicSharedMemorySize, attn_smem);
    cudaFuncSetAttribute(gemm_tf32,
                         cudaFuncAttributeMaxDynamicSharedMemorySize, GEMM_SMEM);

    // 1) per-head QKV projections
    dim3 gq(1, T_DIM / 128, H_DIM);
    gemm_tf32<<<gq, 256, GEMM_SMEM>>>(x, wq, nullptr, q, T_DIM, D_DIM, E_DIM,
                                      (long)E_DIM * D_DIM, (long)T_DIM * D_DIM, 0);
    gemm_tf32<<<gq, 256, GEMM_SMEM>>>(x, wk, nullptr, k, T_DIM, D_DIM, E_DIM,
                                      (long)E_DIM * D_DIM, (long)T_DIM * D_DIM, 0);
    gemm_tf32<<<gq, 256, GEMM_SMEM>>>(x, wv, nullptr, v, T_DIM, D_DIM, E_DIM,
                                      (long)E_DIM * D_DIM, (long)T_DIM * D_DIM, 0);

    // 2) causal attention -> concat [T, H*D]
    attn_tile_kernel<<<dim3(T_DIM / 64, H_DIM), 256, attn_smem>>>(q, k, v, concat);

    // 3) pooling projection
    gemm_tf32<<<dim3(E_DIM / 64, T_DIM / 128, 1), 256, GEMM_SMEM>>>(
        concat, pool_w, nullptr, attn, T_DIM, E_DIM, E_DIM, 0, 0, 0);

    // 4) h = LN(x + attn_out)
    add_ln_kernel<<<T_DIM, 256>>>(x, attn, gamma, beta, hbuf);

    // 5) ffn1 = relu(h @ l1_w + l1_b)
    gemm_tf32<<<dim3(F_DIM / 64, T_DIM / 128, 1), 256, GEMM_SMEM>>>(
        hbuf, l1_w, l1_b, ffn1, T_DIM, F_DIM, E_DIM, 0, 0, 3);

    // 6) ffn2 = ffn1 @ l2_w + l2_b
    gemm_tf32<<<dim3(E_DIM / 64, T_DIM / 128, 1), 256, GEMM_SMEM>>>(
        ffn1, l2_w, l2_b, ffn2, T_DIM, E_DIM, F_DIM, 0, 0, 1);

    // 7) out = LN(h + ffn2)
    add_ln_kernel<<<T_DIM, 256>>>(hbuf, ffn2, gamma, beta, out);
}

// round 15
// speedup vs baseline: 6.2300x; 1.0902x over previous
#include <cuda_runtime.h>
#include <math.h>
#include <stdint.h>

#define T_DIM 2048
#define E_DIM 1024
#define H_DIM 16
#define D_DIM 64
#define F_DIM 4096
#define LN_EPS 1e-5f

// ---------------- scratch (device globals; allocation-free) ----------------
__device__ float g_q[H_DIM * T_DIM * D_DIM];       // [H][T][D]
__device__ float g_k[H_DIM * T_DIM * D_DIM];
__device__ float g_v[H_DIM * T_DIM * D_DIM];
__device__ float g_concat[T_DIM * H_DIM * D_DIM];  // [T][H*D]
__device__ float g_attn[T_DIM * E_DIM];
__device__ float g_hbuf[T_DIM * E_DIM];
__device__ float g_ffn1[T_DIM * F_DIM];
__device__ float g_ffn2[T_DIM * E_DIM];

__device__ __forceinline__ float tf32r(float x) {
    float y;
    asm("cvt.rna.tf32.f32 %0, %1;" : "=f"(y) : "f"(x));
    return y;
}

__device__ __forceinline__ void mma_tf32(float c[4], uint32_t a0, uint32_t a1,
                                         uint32_t a2, uint32_t a3,
                                         uint32_t b0, uint32_t b1) {
    asm volatile(
        "mma.sync.aligned.m16n8k8.row.col.f32.tf32.tf32.f32 "
        "{%0,%1,%2,%3}, {%4,%5,%6,%7}, {%8,%9}, {%0,%1,%2,%3};\n"
        : "+f"(c[0]), "+f"(c[1]), "+f"(c[2]), "+f"(c[3])
        : "r"(a0), "r"(a1), "r"(a2), "r"(a3), "r"(b0), "r"(b1));
}

// ---------------- tf32 tensor-core GEMM (verified R13) ---------------------
#define AS_S 133
#define BS_S 72
#define GEMM_SMEM ((2 * 32 * AS_S + 2 * 32 * BS_S) * 4)

__global__ void __launch_bounds__(256)
gemm_tf32(const float* __restrict__ A, const float* __restrict__ Bm,
          const float* __restrict__ bias, float* __restrict__ Cm,
          int M, int N, int K, long sB, long sC, int flags)
{
    extern __shared__ float sm[];
    float* Asm = sm;                       // [2][32][AS_S]  ([k][m])
    float* Bsm = sm + 2 * 32 * AS_S;       // [2][32][BS_S]  ([k][n])

    const float* B = Bm + (long)blockIdx.z * sB;
    float* C = Cm + (long)blockIdx.z * sC;

    const int tid = threadIdx.x;
    const int warp = tid >> 5, lane = tid & 31;
    const int g = lane >> 2, tig = lane & 3;
    const int wm = (warp >> 1) * 32;
    const int wn = (warp & 1) * 32;

    float c[2][4][4];
    #pragma unroll
    for (int mt = 0; mt < 2; mt++)
        #pragma unroll
        for (int nt = 0; nt < 4; nt++)
            #pragma unroll
            for (int e = 0; e < 4; e++) c[mt][nt][e] = 0.0f;

    const int rowA = tid >> 3;
    const int kgA  = (tid & 7) * 4;
    const float* Agp = A + (long)(blockIdx.y * 128 + rowA) * K + kgA;
    const int rowB = tid >> 4;
    const int cgB  = (tid & 15) * 4;
    const float* Bgp = B + (long)rowB * N + blockIdx.x * 64 + cgB;

    const int KT = K >> 5;
    float4 aS[4], bS[2];

    #pragma unroll
    for (int u = 0; u < 4; u++) aS[u] = *(const float4*)(Agp + (long)(32 * u) * K);
    #pragma unroll
    for (int u = 0; u < 2; u++) bS[u] = *(const float4*)(Bgp + (long)(16 * u) * N);

    int buf = 0;
    for (int kt = 0; kt < KT; kt++) {
        float* Ab = Asm + buf * (32 * AS_S);
        float* Bb = Bsm + buf * (32 * BS_S);
        #pragma unroll
        for (int u = 0; u < 4; u++) {
            int m = rowA + 32 * u;
            Ab[(kgA + 0) * AS_S + m] = tf32r(aS[u].x);
            Ab[(kgA + 1) * AS_S + m] = tf32r(aS[u].y);
            Ab[(kgA + 2) * AS_S + m] = tf32r(aS[u].z);
            Ab[(kgA + 3) * AS_S + m] = tf32r(aS[u].w);
        }
        #pragma unroll
        for (int u = 0; u < 2; u++) {
            int kr = rowB + 16 * u;
            float4 t;
            t.x = tf32r(bS[u].x); t.y = tf32r(bS[u].y);
            t.z = tf32r(bS[u].z); t.w = tf32r(bS[u].w);
            *(float4*)&Bb[kr * BS_S + cgB] = t;
        }
        __syncthreads();

        if (kt + 1 < KT) {
            long k0 = (long)(kt + 1) * 32;
            #pragma unroll
            for (int u = 0; u < 4; u++)
                aS[u] = *(const float4*)(Agp + (long)(32 * u) * K + k0);
            #pragma unroll
            for (int u = 0; u < 2; u++)
                bS[u] = *(const float4*)(Bgp + (k0 + 16 * u) * N);
        }

        #pragma unroll
        for (int ks = 0; ks < 4; ks++) {
            const int kb = ks * 8;
            uint32_t af[2][4], bf[4][2];
            #pragma unroll
            for (int mt = 0; mt < 2; mt++) {
                int mb = wm + mt * 16;
                af[mt][0] = __float_as_uint(Ab[(kb + tig) * AS_S + mb + g]);
                af[mt][1] = __float_as_uint(Ab[(kb + tig) * AS_S + mb + g + 8]);
                af[mt][2] = __float_as_uint(Ab[(kb + tig + 4) * AS_S + mb + g]);
                af[mt][3] = __float_as_uint(Ab[(kb + tig + 4) * AS_S + mb + g + 8]);
            }
            #pragma unroll
            for (int nt = 0; nt < 4; nt++) {
                int nb = wn + nt * 8;
                bf[nt][0] = __float_as_uint(Bb[(kb + tig) * BS_S + nb + g]);
                bf[nt][1] = __float_as_uint(Bb[(kb + tig + 4) * BS_S + nb + g]);
            }
            #pragma unroll
            for (int mt = 0; mt < 2; mt++)
                #pragma unroll
                for (int nt = 0; nt < 4; nt++)
                    mma_tf32(c[mt][nt], af[mt][0], af[mt][1], af[mt][2], af[mt][3],
                             bf[nt][0], bf[nt][1]);
        }
        buf ^= 1;
    }

    #pragma unroll
    for (int mt = 0; mt < 2; mt++) {
        #pragma unroll
        for (int nt = 0; nt < 4; nt++) {
            int row0 = blockIdx.y * 128 + wm + mt * 16 + g;
            int col = blockIdx.x * 64 + wn + nt * 8 + tig * 2;
            float b0 = 0.f, b1 = 0.f;
            if (flags & 1) { b0 = bias[col]; b1 = bias[col + 1]; }
            float v00 = c[mt][nt][0] + b0, v01 = c[mt][nt][1] + b1;
            float v10 = c[mt][nt][2] + b0, v11 = c[mt][nt][3] + b1;
            if (flags & 2) {
                v00 = fmaxf(v00, 0.f); v01 = fmaxf(v01, 0.f);
                v10 = fmaxf(v10, 0.f); v11 = fmaxf(v11, 0.f);
            }
            *(float2*)&C[(long)row0 * N + col] = make_float2(v00, v01);
            *(float2*)&C[(long)(row0 + 8) * N + col] = make_float2(v10, v11);
        }
    }
}

// ---------------- tensor-core tiled causal flash attention ----------------
#define QS_S 65
#define VS_S 68
#define ATTN_SMEM ((3 * 64 * QS_S + 64 * VS_S + 64 * 2 + 3 * 64) * 4)

__global__ void __launch_bounds__(256)
attn_tile_kernel(const float* __restrict__ q, const float* __restrict__ k,
                 const float* __restrict__ v, float* __restrict__ outc)
{
    extern __shared__ float sm[];
    float* Qs = sm;                      // [64 d][QS_S] (q-index inner)
    float* Ks = Qs + 64 * QS_S;          // [64 d][QS_S] (j-index inner)
    float* Ps = Ks + 64 * QS_S;          // [64 j][QS_S] (q-index inner)
    float* Vs = Ps + 64 * QS_S;          // [64 j][VS_S] (d-index inner)
    float* red = Vs + 64 * VS_S;         // [64][2]
    float* mrow = red + 64 * 2;          // 64
    float* lrow = mrow + 64;             // 64
    float* srow = lrow + 64;             // 64

    const int q0 = blockIdx.x * 64;
    const int h = blockIdx.y;
    const int tid = threadIdx.x;
    const int warp = tid >> 5, lane = tid & 31;
    const int g = lane >> 2, tig = lane & 3;
    const int wm = (warp >> 1) * 16;     // q-rows of this warp
    const int wn = (warp & 1) * 32;      // col tile (j for S, d for O)

    const float* qbase = q + ((long)h * T_DIM + q0) * D_DIM;
    const float* kbase = k + (long)h * T_DIM * D_DIM;
    const float* vbase = v + (long)h * T_DIM * D_DIM;

    // load Q transposed: Qs[d][row], pre-scaled by 1/sqrt(D), tf32
    #pragma unroll
    for (int u = 0; u < 4; u++) {
        int f4 = tid + 256 * u;
        int row = f4 >> 4, d4 = (f4 & 15) * 4;
        float4 a = *(const float4*)(qbase + (long)row * D_DIM + d4);
        Qs[(d4 + 0) * QS_S + row] = tf32r(a.x * 0.125f);
        Qs[(d4 + 1) * QS_S + row] = tf32r(a.y * 0.125f);
        Qs[(d4 + 2) * QS_S + row] = tf32r(a.z * 0.125f);
        Qs[(d4 + 3) * QS_S + row] = tf32r(a.w * 0.125f);
    }
    if (tid < 64) { mrow[tid] = -INFINITY; lrow[tid] = 0.0f; }

    // O accumulator fragments: rows wm+g / wm+g+8, cols wn + nt*8 + tig*2 (+1)
    float co[4][4];
    #pragma unroll
    for (int nt = 0; nt < 4; nt++)
        #pragma unroll
        for (int e = 0; e < 4; e++) co[nt][e] = 0.0f;

    for (int j0 = 0; j0 <= q0; j0 += 64) {
        __syncthreads();
        // load K transposed (Ks[d][j]) and V natural (Vs[j][d]), tf32
        #pragma unroll
        for (int u = 0; u < 4; u++) {
            int f4 = tid + 256 * u;
            int row = f4 >> 4, d4 = (f4 & 15) * 4;
            float4 a = *(const float4*)(kbase + (long)(j0 + row) * D_DIM + d4);
            Ks[(d4 + 0) * QS_S + row] = tf32r(a.x);
            Ks[(d4 + 1) * QS_S + row] = tf32r(a.y);
            Ks[(d4 + 2) * QS_S + row] = tf32r(a.z);
            Ks[(d4 + 3) * QS_S + row] = tf32r(a.w);
            float4 b = *(const float4*)(vbase + (long)(j0 + row) * D_DIM + d4);
            float4 t;
            t.x = tf32r(b.x); t.y = tf32r(b.y);
            t.z = tf32r(b.z); t.w = tf32r(b.w);
            *(float4*)&Vs[row * VS_S + d4] = t;
        }
        __syncthreads();

        // S = Q @ K^T via mma: K-dim = 64 (8 k-steps), warp tile 16x32
        float cs[4][4];
        #pragma unroll
        for (int nt = 0; nt < 4; nt++)
            #pragma unroll
            for (int e = 0; e < 4; e++) cs[nt][e] = 0.0f;

        #pragma unroll
        for (int ks = 0; ks < 8; ks++) {
            const int kb = ks * 8;
            uint32_t a0 = __float_as_uint(Qs[(kb + tig) * QS_S + wm + g]);
            uint32_t a1 = __float_as_uint(Qs[(kb + tig) * QS_S + wm + g + 8]);
            uint32_t a2 = __float_as_uint(Qs[(kb + tig + 4) * QS_S + wm + g]);
            uint32_t a3 = __float_as_uint(Qs[(kb + tig + 4) * QS_S + wm + g + 8]);
            #pragma unroll
            for (int nt = 0; nt < 4; nt++) {
                int nb = wn + nt * 8;
                uint32_t b0 = __float_as_uint(Ks[(kb + tig) * QS_S + nb + g]);
                uint32_t b1 = __float_as_uint(Ks[(kb + tig + 4) * QS_S + nb + g]);
                mma_tf32(cs[nt], a0, a1, a2, a3, b0, b1);
            }
        }

        // causal mask on the diagonal tile
        if (j0 == q0) {
            int r0 = wm + g, r1 = wm + g + 8;
            #pragma unroll
            for (int nt = 0; nt < 4; nt++) {
                int col = wn + nt * 8 + tig * 2;
                if (col > r0)     cs[nt][0] = -1e30f;
                if (col + 1 > r0) cs[nt][1] = -1e30f;
                if (col > r1)     cs[nt][2] = -1e30f;
                if (col + 1 > r1) cs[nt][3] = -1e30f;
            }
        }

        // per-row max: thread-local over 8 cols, shfl over tig, smem over n-warps
        {
            float m0 = -INFINITY, m1 = -INFINITY;
            #pragma unroll
            for (int nt = 0; nt < 4; nt++) {
                m0 = fmaxf(m0, fmaxf(cs[nt][0], cs[nt][1]));
                m1 = fmaxf(m1, fmaxf(cs[nt][2], cs[nt][3]));
            }
            m0 = fmaxf(m0, __shfl_xor_sync(0xffffffffu, m0, 1));
            m0 = fmaxf(m0, __shfl_xor_sync(0xffffffffu, m0, 2));
            m1 = fmaxf(m1, __shfl_xor_sync(0xffffffffu, m1, 1));
            m1 = fmaxf(m1, __shfl_xor_sync(0xffffffffu, m1, 2));
            if (tig == 0) {
                red[(wm + g) * 2 + (warp & 1)] = m0;
                red[(wm + g + 8) * 2 + (warp & 1)] = m1;
            }
        }
        __syncthreads();
        if (tid < 64) {
            float mx = fmaxf(red[tid * 2], red[tid * 2 + 1]);
            float mo = mrow[tid];
            float mn = fmaxf(mo, mx);
            srow[tid] = __expf(mo - mn);   // 0 on first tile
            mrow[tid] = mn;
        }
        __syncthreads();

        // P = exp(S - m): store j-major into Ps, accumulate row sums, rescale O
        {
            int r0 = wm + g, r1 = wm + g + 8;
            float mn0 = mrow[r0], mn1 = mrow[r1];
            float sc0 = srow[r0], sc1 = srow[r1];
            float rs0 = 0.f, rs1 = 0.f;
            #pragma unroll
            for (int nt = 0; nt < 4; nt++) {
                int col = wn + nt * 8 + tig * 2;
                float p00 = __expf(cs[nt][0] - mn0);
                float p01 = __expf(cs[nt][1] - mn0);
                float p10 = __expf(cs[nt][2] - mn1);
                float p11 = __expf(cs[nt][3] - mn1);
                rs0 += p00 + p01;
                rs1 += p10 + p11;
                Ps[col * QS_S + r0]       = tf32r(p00);
                Ps[(col + 1) * QS_S + r0] = tf32r(p01);
                Ps[col * QS_S + r1]       = tf32r(p10);
                Ps[(col + 1) * QS_S + r1] = tf32r(p11);
                co[nt][0] *= sc0; co[nt][1] *= sc0;
                co[nt][2] *= sc1; co[nt][3] *= sc1;
            }
            rs0 += __shfl_xor_sync(0xffffffffu, rs0, 1);
            rs0 += __shfl_xor_sync(0xffffffffu, rs0, 2);
            rs1 += __shfl_xor_sync(0xffffffffu, rs1, 1);
            rs1 += __shfl_xor_sync(0xffffffffu, rs1, 2);
            if (tig == 0) {
                red[r0 * 2 + (warp & 1)] = rs0;
                red[r1 * 2 + (warp & 1)] = rs1;
            }
        }
        __syncthreads();
        if (tid < 64)
            lrow[tid] = lrow[tid] * srow[tid] + red[tid * 2] + red[tid * 2 + 1];

        // O += P @ V via mma: K-dim = 64 (j), warp tile 16 q x 32 d
        #pragma unroll
        for (int ks = 0; ks < 8; ks++) {
            const int kb = ks * 8;
            uint32_t a0 = __float_as_uint(Ps[(kb + tig) * QS_S + wm + g]);
            uint32_t a1 = __float_as_uint(Ps[(kb + tig) * QS_S + wm + g + 8]);
            uint32_t a2 = __float_as_uint(Ps[(kb + tig + 4) * QS_S + wm + g]);
            uint32_t a3 = __float_as_uint(Ps[(kb + tig + 4) * QS_S + wm + g + 8]);
            #pragma unroll
            for (int nt = 0; nt < 4; nt++) {
                int nb = wn + nt * 8;
                uint32_t b0 = __float_as_uint(Vs[(kb + tig) * VS_S + nb + g]);
                uint32_t b1 = __float_as_uint(Vs[(kb + tig + 4) * VS_S + nb + g]);
                mma_tf32(co[nt], a0, a1, a2, a3, b0, b1);
            }
        }
    }
    __syncthreads();

    // write O / l to concat layout
    {
        int r0 = wm + g, r1 = wm + g + 8;
        float inv0 = 1.0f / lrow[r0];
        float inv1 = 1.0f / lrow[r1];
        #pragma unroll
        for (int nt = 0; nt < 4; nt++) {
            int col = wn + nt * 8 + tig * 2;
            long b0 = (long)(q0 + r0) * (H_DIM * D_DIM) + h * D_DIM + col;
            long b1 = (long)(q0 + r1) * (H_DIM * D_DIM) + h * D_DIM + col;
            *(float2*)&outc[b0] = make_float2(co[nt][0] * inv0, co[nt][1] * inv0);
            *(float2*)&outc[b1] = make_float2(co[nt][2] * inv1, co[nt][3] * inv1);
        }
    }
}

// ---------------- fused residual add + LayerNorm ---------------------------
__global__ void add_ln_kernel(const float* __restrict__ a, const float* __restrict__ b,
                              const float* __restrict__ gamma, const float* __restrict__ beta,
                              float* __restrict__ out)
{
    const int row = blockIdx.x;
    const int tid = threadIdx.x;
    const float* ar = a + (long)row * E_DIM;
    const float* br = b + (long)row * E_DIM;

    float v[4];
    float s = 0.f, s2 = 0.f;
    #pragma unroll
    for (int u = 0; u < 4; u++) {
        int i = tid + 256 * u;
        float x = ar[i] + br[i];
        v[u] = x;
        s += x;
        s2 += x * x;
    }
    #pragma unroll
    for (int off = 16; off; off >>= 1) {
        s  += __shfl_xor_sync(0xffffffffu, s, off);
        s2 += __shfl_xor_sync(0xffffffffu, s2, off);
    }
    __shared__ float rs[8], rs2[8];
    int w = tid >> 5, ln = tid & 31;
    if (ln == 0) { rs[w] = s; rs2[w] = s2; }
    __syncthreads();
    s = 0.f; s2 = 0.f;
    #pragma unroll
    for (int i = 0; i < 8; i++) { s += rs[i]; s2 += rs2[i]; }

    const float mean = s * (1.0f / E_DIM);
    const float var  = s2 * (1.0f / E_DIM) - mean * mean;
    const float rstd = rsqrtf(var + LN_EPS);
    const float gg = gamma[0];

    #pragma unroll
    for (int u = 0; u < 4; u++) {
        int i = tid + 256 * u;
        out[(long)row * E_DIM + i] = gg * (v[u] - mean) * rstd + beta[i];
    }
}

// ---------------- launch ----------------------------------------------------
extern "C" void kernel_launch(void* const* d_in, const int* in_sizes, int n_in,
                              void* d_out, int out_size)
{
    const float* x      = (const float*)d_in[0];
    const float* wq     = (const float*)d_in[1];
    const float* wk     = (const float*)d_in[2];
    const float* wv     = (const float*)d_in[3];
    const float* pool_w = (const float*)d_in[4];
    const float* l1_w   = (const float*)d_in[5];
    const float* l1_b   = (const float*)d_in[6];
    const float* l2_w   = (const float*)d_in[7];
    const float* l2_b   = (const float*)d_in[8];
    const float* gamma  = (const float*)d_in[9];
    const float* beta   = (const float*)d_in[10];
    float* out = (float*)d_out;

    float *q, *k, *v, *concat, *attn, *hbuf, *ffn1, *ffn2;
    cudaGetSymbolAddress((void**)&q,      g_q);
    cudaGetSymbolAddress((void**)&k,      g_k);
    cudaGetSymbolAddress((void**)&v,      g_v);
    cudaGetSymbolAddress((void**)&concat, g_concat);
    cudaGetSymbolAddress((void**)&attn,   g_attn);
    cudaGetSymbolAddress((void**)&hbuf,   g_hbuf);
    cudaGetSymbolAddress((void**)&ffn1,   g_ffn1);
    cudaGetSymbolAddress((void**)&ffn2,   g_ffn2);

    cudaFuncSetAttribute(attn_tile_kernel,
                         cudaFuncAttributeMaxDynamicSharedMemorySize, ATTN_SMEM);
    cudaFuncSetAttribute(gemm_tf32,
                         cudaFuncAttributeMaxDynamicSharedMemorySize, GEMM_SMEM);

    // 1) per-head QKV projections
    dim3 gq(1, T_DIM / 128, H_DIM);
    gemm_tf32<<<gq, 256, GEMM_SMEM>>>(x, wq, nullptr, q, T_DIM, D_DIM, E_DIM,
                                      (long)E_DIM * D_DIM, (long)T_DIM * D_DIM, 0);
    gemm_tf32<<<gq, 256, GEMM_SMEM>>>(x, wk, nullptr, k, T_DIM, D_DIM, E_DIM,
                                      (long)E_DIM * D_DIM, (long)T_DIM * D_DIM, 0);
    gemm_tf32<<<gq, 256, GEMM_SMEM>>>(x, wv, nullptr, v, T_DIM, D_DIM, E_DIM,
                                      (long)E_DIM * D_DIM, (long)T_DIM * D_DIM, 0);

    // 2) causal attention -> concat [T, H*D]
    attn_tile_kernel<<<dim3(T_DIM / 64, H_DIM), 256, ATTN_SMEM>>>(q, k, v, concat);

    // 3) pooling projection
    gemm_tf32<<<dim3(E_DIM / 64, T_DIM / 128, 1), 256, GEMM_SMEM>>>(
        concat, pool_w, nullptr, attn, T_DIM, E_DIM, E_DIM, 0, 0, 0);

    // 4) h = LN(x + attn_out)
    add_ln_kernel<<<T_DIM, 256>>>(x, attn, gamma, beta, hbuf);

    // 5) ffn1 = relu(h @ l1_w + l1_b)
    gemm_tf32<<<dim3(F_DIM / 64, T_DIM / 128, 1), 256, GEMM_SMEM>>>(
        hbuf, l1_w, l1_b, ffn1, T_DIM, F_DIM, E_DIM, 0, 0, 3);

    // 6) ffn2 = ffn1 @ l2_w + l2_b
    gemm_tf32<<<dim3(E_DIM / 64, T_DIM / 128, 1), 256, GEMM_SMEM>>>(
        ffn1, l2_w, l2_b, ffn2, T_DIM, E_DIM, F_DIM, 0, 0, 1);

    // 7) out = LN(h + ffn2)
    add_ln_kernel<<<T_DIM, 256>>>(hbuf, ffn2, gamma, beta, out);
}